// round 1
// baseline (speedup 1.0000x reference)
#include <cuda_runtime.h>
#include <cstddef>

#define NTOK   1024
#define BATCH  32
#define HEADS  8
#define DHEAD  64
#define INNER  512
#define QKV3   (3*INNER)

// Scratch (static device globals; allocation in kernel_launch is forbidden)
__device__ float g_qkv [(size_t)BATCH*NTOK*QKV3];   // 201 MB: x @ w_qkv
__device__ float g_bias[(size_t)HEADS*NTOK*NTOK];   // 33.5 MB: bias_table[rel_index] per head
__device__ float g_att [(size_t)BATCH*NTOK*INNER];  // 67 MB: attention output

// ---------------------------------------------------------------------------
// bias[h][n][m] = bias_table[rel_index[n][m]][h]
// ---------------------------------------------------------------------------
__global__ void bias_kernel(const float* __restrict__ bias_table,
                            const int*   __restrict__ rel_index) {
    int idx = blockIdx.x * blockDim.x + threadIdx.x;   // over N*N
    if (idx >= NTOK * NTOK) return;
    int r = rel_index[idx];
#pragma unroll
    for (int h = 0; h < HEADS; h++)
        g_bias[(size_t)h * NTOK * NTOK + idx] = bias_table[r * HEADS + h];
}

// ---------------------------------------------------------------------------
// C[M,Nn] = A[M,K] @ B[K,Nn] (+ bias[Nn]); 64x64 block, BK=16, 4x4 per thread
// ---------------------------------------------------------------------------
template<bool ADD_B>
__global__ __launch_bounds__(256)
void gemm_kernel(const float* __restrict__ A, const float* __restrict__ B,
                 float* __restrict__ C, const float* __restrict__ bias,
                 int M, int Nn, int K) {
    __shared__ float As[16][68];   // [k][m] (transposed A tile)
    __shared__ float Bs[16][68];   // [k][n]
    const int tid = threadIdx.x;
    const int tx = tid & 15, ty = tid >> 4;
    const int bm = blockIdx.y * 64, bn = blockIdx.x * 64;
    const int a_row = tid >> 2,  a_col = (tid & 3) << 2;   // 64 rows x 16 k
    const int b_row = tid >> 4,  b_col = (tid & 15) << 2;  // 16 k x 64 n

    float acc[4][4] = {};
    const float* Aptr = A + (size_t)(bm + a_row) * K + a_col;
    const float* Bptr = B + (size_t)b_row * Nn + bn + b_col;

    for (int k0 = 0; k0 < K; k0 += 16) {
        float4 av = *(const float4*)(Aptr + k0);
        float4 bv = *(const float4*)(Bptr + (size_t)k0 * Nn);
        As[a_col + 0][a_row] = av.x;
        As[a_col + 1][a_row] = av.y;
        As[a_col + 2][a_row] = av.z;
        As[a_col + 3][a_row] = av.w;
        *(float4*)&Bs[b_row][b_col] = bv;
        __syncthreads();
#pragma unroll
        for (int k = 0; k < 16; k++) {
            float4 a4 = *(const float4*)&As[k][ty * 4];
            float4 b4 = *(const float4*)&Bs[k][tx * 4];
            float ar[4] = {a4.x, a4.y, a4.z, a4.w};
            float br[4] = {b4.x, b4.y, b4.z, b4.w};
#pragma unroll
            for (int r = 0; r < 4; r++)
#pragma unroll
                for (int c = 0; c < 4; c++)
                    acc[r][c] = fmaf(ar[r], br[c], acc[r][c]);
        }
        __syncthreads();
    }

#pragma unroll
    for (int r = 0; r < 4; r++) {
        size_t row = (size_t)bm + ty * 4 + r;
        float4 o = make_float4(acc[r][0], acc[r][1], acc[r][2], acc[r][3]);
        if (ADD_B) {
            int col = bn + tx * 4;
            o.x += bias[col + 0]; o.y += bias[col + 1];
            o.z += bias[col + 2]; o.w += bias[col + 3];
        }
        *(float4*)&C[row * Nn + bn + tx * 4] = o;
    }
}

// ---------------------------------------------------------------------------
// Flash-style attention: one block = (batch b, head h, 64-row tile rb).
// Q,K live transposed in SMEM ([d][m]) so the inner product loop reads both
// operands as contiguous float4 (bank-conflict free). Online softmax.
// ---------------------------------------------------------------------------
__global__ __launch_bounds__(256)
void attn_kernel() {
    __shared__ float QT[64][64];   // Q^T: [d][i]
    __shared__ float B1[64][64];   // K^T: [d][m], then V: [m][d]
    __shared__ float Ss[64][64];   // bias tile, then P

    const int tid = threadIdx.x;
    const int tx = tid & 15, ty = tid >> 4;
    const int rb = blockIdx.x;          // 0..15
    const int h  = blockIdx.y;          // 0..7
    const int b  = blockIdx.z;          // 0..31
    const int bm = rb * 64;

    const float* qbase = g_qkv + (size_t)b * NTOK * QKV3 + h * DHEAD;
    const float* kbase = qbase + INNER;
    const float* vbase = qbase + 2 * INNER;
    const float* biasb = g_bias + (size_t)h * NTOK * NTOK;

    const int lm = tid >> 2;            // loader: row within tile (0..63)
    const int ld0 = (tid & 3) << 4;     // loader: d base (0,16,32,48)

    // Load Q tile transposed
    {
        const float* p = qbase + (size_t)(bm + lm) * QKV3 + ld0;
#pragma unroll
        for (int j = 0; j < 4; j++) {
            float4 v = *(const float4*)(p + j * 4);
            QT[ld0 + j * 4 + 0][lm] = v.x;
            QT[ld0 + j * 4 + 1][lm] = v.y;
            QT[ld0 + j * 4 + 2][lm] = v.z;
            QT[ld0 + j * 4 + 3][lm] = v.w;
        }
    }

    float O[4][4] = {};
    float mrow[4] = {-1e30f, -1e30f, -1e30f, -1e30f};
    float lrow[4] = {};
    const float scale = 0.125f;   // 64^-0.5

    for (int t = 0; t < 16; t++) {
        __syncthreads();  // protect B1/Ss reuse (and QT readiness on t=0)
        // Load K tile transposed into B1, bias tile into Ss
        {
            const float* p = kbase + (size_t)(t * 64 + lm) * QKV3 + ld0;
#pragma unroll
            for (int j = 0; j < 4; j++) {
                float4 v = *(const float4*)(p + j * 4);
                B1[ld0 + j * 4 + 0][lm] = v.x;
                B1[ld0 + j * 4 + 1][lm] = v.y;
                B1[ld0 + j * 4 + 2][lm] = v.z;
                B1[ld0 + j * 4 + 3][lm] = v.w;
            }
            const float* bp = biasb + (size_t)(bm + lm) * NTOK + t * 64 + ld0;
#pragma unroll
            for (int j = 0; j < 4; j++)
                *(float4*)&Ss[lm][ld0 + j * 4] = *(const float4*)(bp + j * 4);
        }
        __syncthreads();

        // S = scale * (Q K^T) + bias
        float s[4][4] = {};
#pragma unroll 8
        for (int d = 0; d < 64; d++) {
            float4 q4 = *(const float4*)&QT[d][ty * 4];
            float4 k4 = *(const float4*)&B1[d][tx * 4];
            float qr[4] = {q4.x, q4.y, q4.z, q4.w};
            float kc[4] = {k4.x, k4.y, k4.z, k4.w};
#pragma unroll
            for (int r = 0; r < 4; r++)
#pragma unroll
                for (int c = 0; c < 4; c++)
                    s[r][c] = fmaf(qr[r], kc[c], s[r][c]);
        }
#pragma unroll
        for (int r = 0; r < 4; r++) {
            float4 bb = *(const float4*)&Ss[ty * 4 + r][tx * 4];
            s[r][0] = fmaf(s[r][0], scale, bb.x);
            s[r][1] = fmaf(s[r][1], scale, bb.y);
            s[r][2] = fmaf(s[r][2], scale, bb.z);
            s[r][3] = fmaf(s[r][3], scale, bb.w);
        }

        // Online softmax update (row stats shared across the 16 tx lanes)
#pragma unroll
        for (int r = 0; r < 4; r++) {
            float mx = fmaxf(fmaxf(s[r][0], s[r][1]), fmaxf(s[r][2], s[r][3]));
#pragma unroll
            for (int off = 8; off >= 1; off >>= 1)
                mx = fmaxf(mx, __shfl_xor_sync(0xffffffffu, mx, off, 16));
            float mnew = fmaxf(mrow[r], mx);
            float corr = __expf(mrow[r] - mnew);
            mrow[r] = mnew;
            float rs = 0.f;
#pragma unroll
            for (int c = 0; c < 4; c++) {
                float p = __expf(s[r][c] - mnew);
                s[r][c] = p;
                rs += p;
            }
#pragma unroll
            for (int off = 8; off >= 1; off >>= 1)
                rs += __shfl_xor_sync(0xffffffffu, rs, off, 16);
            lrow[r] = lrow[r] * corr + rs;
#pragma unroll
            for (int c = 0; c < 4; c++) O[r][c] *= corr;
        }

        // Write P into Ss (each thread overwrites exactly the bias slots it read)
#pragma unroll
        for (int r = 0; r < 4; r++)
            *(float4*)&Ss[ty * 4 + r][tx * 4] =
                make_float4(s[r][0], s[r][1], s[r][2], s[r][3]);
        __syncthreads();   // all done with K tile; P visible

        // Load V tile (natural layout) into B1
        {
            const float* p = vbase + (size_t)(t * 64 + lm) * QKV3 + ld0;
#pragma unroll
            for (int j = 0; j < 4; j++)
                *(float4*)&B1[lm][ld0 + j * 4] = *(const float4*)(p + j * 4);
        }
        __syncthreads();

        // O += P @ V
#pragma unroll 8
        for (int j = 0; j < 64; j++) {
            float pr[4];
#pragma unroll
            for (int r = 0; r < 4; r++) pr[r] = Ss[ty * 4 + r][j];
            float4 v4 = *(const float4*)&B1[j][tx * 4];
            float vc[4] = {v4.x, v4.y, v4.z, v4.w};
#pragma unroll
            for (int r = 0; r < 4; r++)
#pragma unroll
                for (int c = 0; c < 4; c++)
                    O[r][c] = fmaf(pr[r], vc[c], O[r][c]);
        }
    }

    // Normalize and write to g_att[b][n][h*64 + d]
#pragma unroll
    for (int r = 0; r < 4; r++) {
        float inv = 1.0f / lrow[r];
        int n = bm + ty * 4 + r;
        float4 o = make_float4(O[r][0] * inv, O[r][1] * inv,
                               O[r][2] * inv, O[r][3] * inv);
        *(float4*)&g_att[((size_t)b * NTOK + n) * INNER + h * DHEAD + tx * 4] = o;
    }
}

// ---------------------------------------------------------------------------
extern "C" void kernel_launch(void* const* d_in, const int* in_sizes, int n_in,
                              void* d_out, int out_size) {
    const float* x          = (const float*)d_in[0];
    const float* w_qkv      = (const float*)d_in[1];
    const float* w_out      = (const float*)d_in[2];
    const float* b_out      = (const float*)d_in[3];
    const float* bias_table = (const float*)d_in[4];
    const int*   rel_index  = (const int*)  d_in[5];
    float* out = (float*)d_out;

    float *qkv, *att;
    cudaGetSymbolAddress((void**)&qkv, g_qkv);
    cudaGetSymbolAddress((void**)&att, g_att);

    const int M = BATCH * NTOK;   // 32768

    // 1) relative-position bias expansion
    bias_kernel<<<(NTOK * NTOK + 255) / 256, 256>>>(bias_table, rel_index);

    // 2) qkv = x @ w_qkv   [32768,512] x [512,1536]
    gemm_kernel<false><<<dim3(QKV3 / 64, M / 64), 256>>>(
        x, w_qkv, qkv, nullptr, M, QKV3, INNER);

    // 3) attention (flash-style, per (b,h,row-tile))
    attn_kernel<<<dim3(NTOK / 64, HEADS, BATCH), 256>>>();

    // 4) out = att @ w_out + b_out   [32768,512] x [512,512]
    gemm_kernel<true><<<dim3(INNER / 64, M / 64), 256>>>(
        att, w_out, out, b_out, M, INNER, INNER);
}

// round 5
// speedup vs baseline: 1.3919x; 1.3919x over previous
#include <cuda_runtime.h>
#include <cuda_bf16.h>
#include <cstdint>
#include <cstddef>

#define NTOK   1024
#define BATCH  32
#define HEADS  8
#define DHEAD  64
#define INNER  512
#define QKV3   (3*INNER)
#define MROWS  (BATCH*NTOK)
#define BK     32

// ---------------- scratch (static device globals; no allocation allowed) ----
__device__ float g_qkv [(size_t)MROWS*QKV3];        // x @ w_qkv (fp32)
__device__ float g_bias[(size_t)HEADS*NTOK*NTOK];   // bias_table[rel_index]
__device__ float g_att [(size_t)MROWS*INNER];       // attention output (fp32)

__device__ __nv_bfloat16 g_x_hi  [(size_t)MROWS*INNER];
__device__ __nv_bfloat16 g_x_lo  [(size_t)MROWS*INNER];
__device__ __nv_bfloat16 g_att_hi[(size_t)MROWS*INNER];
__device__ __nv_bfloat16 g_att_lo[(size_t)MROWS*INNER];
__device__ __nv_bfloat16 g_wqkvT_hi[(size_t)QKV3*INNER];   // [N,K] transposed
__device__ __nv_bfloat16 g_wqkvT_lo[(size_t)QKV3*INNER];
__device__ __nv_bfloat16 g_woutT_hi[(size_t)INNER*INNER];
__device__ __nv_bfloat16 g_woutT_lo[(size_t)INNER*INNER];

// ---------------- PTX helpers (base sm_103-safe: no tcgen05) ----------------
__device__ __forceinline__ uint32_t smem_u32(const void* p) {
    uint32_t a;
    asm("{ .reg .u64 t; cvta.to.shared.u64 t, %1; cvt.u32.u64 %0, t; }"
        : "=r"(a) : "l"(p));
    return a;
}
__device__ __forceinline__ void cp16(uint32_t dst, const void* src) {
    asm volatile("cp.async.cg.shared.global [%0], [%1], 16;"
                 :: "r"(dst), "l"(src) : "memory");
}
#define CP_COMMIT() asm volatile("cp.async.commit_group;" ::: "memory")
#define CP_WAIT1()  asm volatile("cp.async.wait_group 1;" ::: "memory")

#define LDSM4(r0, r1, r2, r3, addr)                                            \
    asm volatile("ldmatrix.sync.aligned.m8n8.x4.shared.b16 {%0,%1,%2,%3}, [%4];" \
                 : "=r"(r0), "=r"(r1), "=r"(r2), "=r"(r3) : "r"(addr))

#define MMA16816(d, a, b)                                                      \
    asm volatile("mma.sync.aligned.m16n8k16.row.col.f32.bf16.bf16.f32 "        \
                 "{%0,%1,%2,%3}, {%4,%5,%6,%7}, {%8,%9}, {%0,%1,%2,%3};"       \
                 : "+f"((d)[0]), "+f"((d)[1]), "+f"((d)[2]), "+f"((d)[3])      \
                 : "r"((a)[0]), "r"((a)[1]), "r"((a)[2]), "r"((a)[3]),         \
                   "r"((b)[0]), "r"((b)[1]))

// ---------------------------------------------------------------------------
// bias[h][n][m] = bias_table[rel_index[n][m]][h]
// ---------------------------------------------------------------------------
__global__ void bias_kernel(const float* __restrict__ bias_table,
                            const int*   __restrict__ rel_index) {
    int idx = blockIdx.x * blockDim.x + threadIdx.x;
    if (idx >= NTOK * NTOK) return;
    int r = rel_index[idx];
#pragma unroll
    for (int h = 0; h < HEADS; h++)
        g_bias[(size_t)h * NTOK * NTOK + idx] = bias_table[r * HEADS + h];
}

// ---------------------------------------------------------------------------
// split fp32 -> (hi, lo) bf16, same layout. n4 = elements/4.
// ---------------------------------------------------------------------------
__global__ void split_kernel(const float* __restrict__ in,
                             __nv_bfloat16* __restrict__ hi,
                             __nv_bfloat16* __restrict__ lo, size_t n4) {
    size_t i = (size_t)blockIdx.x * blockDim.x + threadIdx.x;
    if (i >= n4) return;
    float4 v = ((const float4*)in)[i];
    float vv[4] = {v.x, v.y, v.z, v.w};
    uint32_t hp[2] = {0, 0}, lp[2] = {0, 0};
#pragma unroll
    for (int j = 0; j < 4; j++) {
        __nv_bfloat16 h = __float2bfloat16(vv[j]);
        float r = vv[j] - __bfloat162float(h);
        __nv_bfloat16 l = __float2bfloat16(r);
        hp[j >> 1] |= (uint32_t)__bfloat16_as_ushort(h) << ((j & 1) * 16);
        lp[j >> 1] |= (uint32_t)__bfloat16_as_ushort(l) << ((j & 1) * 16);
    }
    ((uint2*)hi)[i] = make_uint2(hp[0], hp[1]);
    ((uint2*)lo)[i] = make_uint2(lp[0], lp[1]);
}

// split + transpose weights: in [K,N] fp32 -> hiT/loT [N,K] bf16
__global__ void splitT_kernel(const float* __restrict__ in,
                              __nv_bfloat16* __restrict__ hiT,
                              __nv_bfloat16* __restrict__ loT, int K, int N) {
    int idx = blockIdx.x * blockDim.x + threadIdx.x;
    if (idx >= K * N) return;
    int n = idx / K, k = idx - n * K;
    float v = in[(size_t)k * N + n];
    __nv_bfloat16 h = __float2bfloat16(v);
    float r = v - __bfloat162float(h);
    hiT[idx] = h;
    loT[idx] = __float2bfloat16(r);
}

// ---------------------------------------------------------------------------
// mma.sync bf16-split GEMM: C = (Ahi+Alo)[M,512] @ (Bhi+Blo)^T[N,512]
// 128x128 CTA tile, 8 warps (2x4) of 64x32, BK=32, 3-stage cp.async ring.
// SMEM per stage: Ahi|Alo|Bhi|Blo, each [128][32] bf16 (64B rows, XOR swizzle).
// ---------------------------------------------------------------------------
#define STAGE_BYTES 32768
#define GSMEM_BYTES (3 * STAGE_BYTES)

template<bool ADD_B>
__global__ __launch_bounds__(256)
void gemm_mma(const __nv_bfloat16* __restrict__ Ahi, const __nv_bfloat16* __restrict__ Alo,
              const __nv_bfloat16* __restrict__ BThi, const __nv_bfloat16* __restrict__ BTlo,
              float* __restrict__ C, const float* __restrict__ bias, int Nn) {
    constexpr int K = 512;
    extern __shared__ char smem[];
    const int tid = threadIdx.x, wid = tid >> 5, lane = tid & 31;
    const int wm = wid >> 2, wn = wid & 3;
    const int bm = blockIdx.y * 128, bn = blockIdx.x * 128;
    const uint32_t sb = smem_u32(smem);

    const __nv_bfloat16* src0 = Ahi  + (size_t)bm * K;
    const __nv_bfloat16* src1 = Alo  + (size_t)bm * K;
    const __nv_bfloat16* src2 = BThi + (size_t)bn * K;
    const __nv_bfloat16* src3 = BTlo + (size_t)bn * K;

    // issue one 32KB stage (2048 x 16B chunks; 8 cp.async per thread)
    auto issue = [&](int stage, int c) {
        const uint32_t d0 = sb + stage * STAGE_BYTES;
        const int k0 = c * BK;
        const __nv_bfloat16* srcs[4] = {src0, src1, src2, src3};
#pragma unroll
        for (int o = 0; o < 4; o++) {
#pragma unroll
            for (int i = 0; i < 2; i++) {
                int cid = tid + 256 * i;
                int row = cid >> 2, ch = cid & 3;
                int cc = ch ^ ((row >> 1) & 3);
                cp16(d0 + o * 8192 + row * 64 + cc * 16,
                     srcs[o] + (size_t)row * K + k0 + ch * 8);
            }
        }
    };

    float acc[4][4][4] = {};   // [mt][nt][reg]

    issue(0, 0); CP_COMMIT();
    issue(1, 1); CP_COMMIT();

    for (int c = 0; c < K / BK; c++) {
        const int s = c % 3;
        CP_WAIT1();
        __syncthreads();          // all warps done with stage (c+2)%3's last use
        if (c + 2 < K / BK) issue((c + 2) % 3, c + 2);
        CP_COMMIT();

        const uint32_t stg = sb + s * STAGE_BYTES;
#pragma unroll
        for (int ks = 0; ks < 2; ks++) {
            uint32_t aH[4][4], aL[4][4], bH[4][2], bL[4][2];
#pragma unroll
            for (int mt = 0; mt < 4; mt++) {
                int row = wm * 64 + mt * 16 + (lane & 15);
                int ch = 2 * ks + (lane >> 4);
                int cc = ch ^ ((row >> 1) & 3);
                uint32_t ad = stg + row * 64 + cc * 16;
                LDSM4(aH[mt][0], aH[mt][1], aH[mt][2], aH[mt][3], ad);
                LDSM4(aL[mt][0], aL[mt][1], aL[mt][2], aL[mt][3], ad + 8192);
            }
#pragma unroll
            for (int np = 0; np < 2; np++) {
                int rown = wn * 32 + np * 16 + (lane & 7) + ((lane >> 4) << 3);
                int ch = 2 * ks + ((lane >> 3) & 1);
                int cc = ch ^ ((rown >> 1) & 3);
                uint32_t bd = stg + 16384 + rown * 64 + cc * 16;
                LDSM4(bH[2*np][0], bH[2*np][1], bH[2*np+1][0], bH[2*np+1][1], bd);
                LDSM4(bL[2*np][0], bL[2*np][1], bL[2*np+1][0], bL[2*np+1][1], bd + 8192);
            }
#pragma unroll
            for (int mt = 0; mt < 4; mt++)
#pragma unroll
                for (int nt = 0; nt < 4; nt++) {
                    MMA16816(acc[mt][nt], aH[mt], bH[nt]);
                    MMA16816(acc[mt][nt], aH[mt], bL[nt]);
                    MMA16816(acc[mt][nt], aL[mt], bH[nt]);
                }
        }
    }

    // epilogue: direct fp32 stores (float2 per fragment half-row)
#pragma unroll
    for (int mt = 0; mt < 4; mt++) {
        int row0 = bm + wm * 64 + mt * 16 + (lane >> 2);
#pragma unroll
        for (int nt = 0; nt < 4; nt++) {
            int col = bn + wn * 32 + nt * 8 + (lane & 3) * 2;
            float2 v0 = make_float2(acc[mt][nt][0], acc[mt][nt][1]);
            float2 v1 = make_float2(acc[mt][nt][2], acc[mt][nt][3]);
            if (ADD_B) {
                float b0 = bias[col], b1 = bias[col + 1];
                v0.x += b0; v0.y += b1; v1.x += b0; v1.y += b1;
            }
            *(float2*)&C[(size_t)row0 * Nn + col]       = v0;
            *(float2*)&C[(size_t)(row0 + 8) * Nn + col] = v1;
        }
    }
}

// ---------------------------------------------------------------------------
// Flash-style SIMT attention (proven in R1 — converts to mma.sync next round)
// ---------------------------------------------------------------------------
__global__ __launch_bounds__(256)
void attn_kernel() {
    __shared__ float QT[64][64];
    __shared__ float B1[64][64];
    __shared__ float Ss[64][64];

    const int tid = threadIdx.x;
    const int tx = tid & 15, ty = tid >> 4;
    const int rb = blockIdx.x, h = blockIdx.y, b = blockIdx.z;
    const int bm = rb * 64;

    const float* qbase = g_qkv + (size_t)b * NTOK * QKV3 + h * DHEAD;
    const float* kbase = qbase + INNER;
    const float* vbase = qbase + 2 * INNER;
    const float* biasb = g_bias + (size_t)h * NTOK * NTOK;

    const int lm = tid >> 2;
    const int ld0 = (tid & 3) << 4;

    {
        const float* p = qbase + (size_t)(bm + lm) * QKV3 + ld0;
#pragma unroll
        for (int j = 0; j < 4; j++) {
            float4 v = *(const float4*)(p + j * 4);
            QT[ld0 + j * 4 + 0][lm] = v.x;
            QT[ld0 + j * 4 + 1][lm] = v.y;
            QT[ld0 + j * 4 + 2][lm] = v.z;
            QT[ld0 + j * 4 + 3][lm] = v.w;
        }
    }

    float O[4][4] = {};
    float mrow[4] = {-1e30f, -1e30f, -1e30f, -1e30f};
    float lrow[4] = {};
    const float scale = 0.125f;

    for (int t = 0; t < 16; t++) {
        __syncthreads();
        {
            const float* p = kbase + (size_t)(t * 64 + lm) * QKV3 + ld0;
#pragma unroll
            for (int j = 0; j < 4; j++) {
                float4 v = *(const float4*)(p + j * 4);
                B1[ld0 + j * 4 + 0][lm] = v.x;
                B1[ld0 + j * 4 + 1][lm] = v.y;
                B1[ld0 + j * 4 + 2][lm] = v.z;
                B1[ld0 + j * 4 + 3][lm] = v.w;
            }
            const float* bp = biasb + (size_t)(bm + lm) * NTOK + t * 64 + ld0;
#pragma unroll
            for (int j = 0; j < 4; j++)
                *(float4*)&Ss[lm][ld0 + j * 4] = *(const float4*)(bp + j * 4);
        }
        __syncthreads();

        float s[4][4] = {};
#pragma unroll 8
        for (int d = 0; d < 64; d++) {
            float4 q4 = *(const float4*)&QT[d][ty * 4];
            float4 k4 = *(const float4*)&B1[d][tx * 4];
            float qr[4] = {q4.x, q4.y, q4.z, q4.w};
            float kc[4] = {k4.x, k4.y, k4.z, k4.w};
#pragma unroll
            for (int r = 0; r < 4; r++)
#pragma unroll
                for (int c = 0; c < 4; c++)
                    s[r][c] = fmaf(qr[r], kc[c], s[r][c]);
        }
#pragma unroll
        for (int r = 0; r < 4; r++) {
            float4 bb = *(const float4*)&Ss[ty * 4 + r][tx * 4];
            s[r][0] = fmaf(s[r][0], scale, bb.x);
            s[r][1] = fmaf(s[r][1], scale, bb.y);
            s[r][2] = fmaf(s[r][2], scale, bb.z);
            s[r][3] = fmaf(s[r][3], scale, bb.w);
        }

#pragma unroll
        for (int r = 0; r < 4; r++) {
            float mx = fmaxf(fmaxf(s[r][0], s[r][1]), fmaxf(s[r][2], s[r][3]));
#pragma unroll
            for (int off = 8; off >= 1; off >>= 1)
                mx = fmaxf(mx, __shfl_xor_sync(0xffffffffu, mx, off, 16));
            float mnew = fmaxf(mrow[r], mx);
            float corr = __expf(mrow[r] - mnew);
            mrow[r] = mnew;
            float rs = 0.f;
#pragma unroll
            for (int c = 0; c < 4; c++) {
                float p = __expf(s[r][c] - mnew);
                s[r][c] = p;
                rs += p;
            }
#pragma unroll
            for (int off = 8; off >= 1; off >>= 1)
                rs += __shfl_xor_sync(0xffffffffu, rs, off, 16);
            lrow[r] = lrow[r] * corr + rs;
#pragma unroll
            for (int c = 0; c < 4; c++) O[r][c] *= corr;
        }

#pragma unroll
        for (int r = 0; r < 4; r++)
            *(float4*)&Ss[ty * 4 + r][tx * 4] =
                make_float4(s[r][0], s[r][1], s[r][2], s[r][3]);
        __syncthreads();

        {
            const float* p = vbase + (size_t)(t * 64 + lm) * QKV3 + ld0;
#pragma unroll
            for (int j = 0; j < 4; j++)
                *(float4*)&B1[lm][ld0 + j * 4] = *(const float4*)(p + j * 4);
        }
        __syncthreads();

#pragma unroll 8
        for (int j = 0; j < 64; j++) {
            float pr[4];
#pragma unroll
            for (int r = 0; r < 4; r++) pr[r] = Ss[ty * 4 + r][j];
            float4 v4 = *(const float4*)&B1[j][tx * 4];
            float vc[4] = {v4.x, v4.y, v4.z, v4.w};
#pragma unroll
            for (int r = 0; r < 4; r++)
#pragma unroll
                for (int c = 0; c < 4; c++)
                    O[r][c] = fmaf(pr[r], vc[c], O[r][c]);
        }
    }

#pragma unroll
    for (int r = 0; r < 4; r++) {
        float inv = 1.0f / lrow[r];
        int n = bm + ty * 4 + r;
        float4 o = make_float4(O[r][0] * inv, O[r][1] * inv,
                               O[r][2] * inv, O[r][3] * inv);
        *(float4*)&g_att[((size_t)b * NTOK + n) * INNER + h * DHEAD + tx * 4] = o;
    }
}

// ---------------------------------------------------------------------------
extern "C" void kernel_launch(void* const* d_in, const int* in_sizes, int n_in,
                              void* d_out, int out_size) {
    const float* x          = (const float*)d_in[0];
    const float* w_qkv      = (const float*)d_in[1];
    const float* w_out      = (const float*)d_in[2];
    const float* b_out      = (const float*)d_in[3];
    const float* bias_table = (const float*)d_in[4];
    const int*   rel_index  = (const int*)  d_in[5];
    float* out = (float*)d_out;

    float *qkv, *att;
    __nv_bfloat16 *xh, *xl, *ah, *al, *wqh, *wql, *woh, *wol;
    cudaGetSymbolAddress((void**)&qkv, g_qkv);
    cudaGetSymbolAddress((void**)&att, g_att);
    cudaGetSymbolAddress((void**)&xh,  g_x_hi);
    cudaGetSymbolAddress((void**)&xl,  g_x_lo);
    cudaGetSymbolAddress((void**)&ah,  g_att_hi);
    cudaGetSymbolAddress((void**)&al,  g_att_lo);
    cudaGetSymbolAddress((void**)&wqh, g_wqkvT_hi);
    cudaGetSymbolAddress((void**)&wql, g_wqkvT_lo);
    cudaGetSymbolAddress((void**)&woh, g_woutT_hi);
    cudaGetSymbolAddress((void**)&wol, g_woutT_lo);

    cudaFuncSetAttribute(gemm_mma<false>, cudaFuncAttributeMaxDynamicSharedMemorySize, GSMEM_BYTES);
    cudaFuncSetAttribute(gemm_mma<true>,  cudaFuncAttributeMaxDynamicSharedMemorySize, GSMEM_BYTES);

    // 1) bias expansion
    bias_kernel<<<(NTOK * NTOK + 255) / 256, 256>>>(bias_table, rel_index);

    // 2) split x and w_qkv (transposed) to bf16 hi/lo
    {
        size_t n4 = (size_t)MROWS * INNER / 4;
        split_kernel<<<(unsigned)((n4 + 255) / 256), 256>>>(x, xh, xl, n4);
        int nw = INNER * QKV3;
        // w_qkv is [K=INNER rows, N=QKV3 cols]  (was swapped — the R3 bug)
        splitT_kernel<<<(nw + 255) / 256, 256>>>(w_qkv, wqh, wql, INNER, QKV3);
    }

    // 3) qkv = x @ w_qkv   via mma.sync split-bf16   [32768,512]x[512,1536]
    gemm_mma<false><<<dim3(QKV3 / 128, MROWS / 128), 256, GSMEM_BYTES>>>(
        xh, xl, wqh, wql, qkv, nullptr, QKV3);

    // 4) attention
    attn_kernel<<<dim3(NTOK / 64, HEADS, BATCH), 256>>>();

    // 5) split att and w_out
    {
        size_t n4 = (size_t)MROWS * INNER / 4;
        split_kernel<<<(unsigned)((n4 + 255) / 256), 256>>>(att, ah, al, n4);
        int nw = INNER * INNER;
        splitT_kernel<<<(nw + 255) / 256, 256>>>(w_out, woh, wol, INNER, INNER);
    }

    // 6) out = att @ w_out + b_out   [32768,512]x[512,512]
    gemm_mma<true><<<dim3(INNER / 128, MROWS / 128), 256, GSMEM_BYTES>>>(
        ah, al, woh, wol, out, b_out, INNER);
}

// round 6
// speedup vs baseline: 2.9392x; 2.1117x over previous
#include <cuda_runtime.h>
#include <cuda_bf16.h>
#include <cstdint>
#include <cstddef>

#define NTOK   1024
#define BATCH  32
#define HEADS  8
#define DHEAD  64
#define INNER  512
#define QKV3   (3*INNER)
#define MROWS  (BATCH*NTOK)
#define BK     32

// ---------------- scratch (static device globals; no allocation allowed) ----
__device__ float g_qkv [(size_t)MROWS*QKV3];              // x @ w_qkv (fp32)
__device__ __nv_bfloat16 g_biasb[(size_t)HEADS*NTOK*NTOK]; // bias (bf16)

__device__ __nv_bfloat16 g_x_hi  [(size_t)MROWS*INNER];
__device__ __nv_bfloat16 g_x_lo  [(size_t)MROWS*INNER];
__device__ __nv_bfloat16 g_att_hi[(size_t)MROWS*INNER];
__device__ __nv_bfloat16 g_att_lo[(size_t)MROWS*INNER];
__device__ __nv_bfloat16 g_wqkvT_hi[(size_t)QKV3*INNER];
__device__ __nv_bfloat16 g_wqkvT_lo[(size_t)QKV3*INNER];
__device__ __nv_bfloat16 g_woutT_hi[(size_t)INNER*INNER];
__device__ __nv_bfloat16 g_woutT_lo[(size_t)INNER*INNER];

// attention operands: Q,K packed [b,h,n,64]; V transposed [b,h,64,n]
__device__ __nv_bfloat16 g_q_hi [(size_t)BATCH*HEADS*NTOK*DHEAD];
__device__ __nv_bfloat16 g_q_lo [(size_t)BATCH*HEADS*NTOK*DHEAD];
__device__ __nv_bfloat16 g_k_hi [(size_t)BATCH*HEADS*NTOK*DHEAD];
__device__ __nv_bfloat16 g_k_lo [(size_t)BATCH*HEADS*NTOK*DHEAD];
__device__ __nv_bfloat16 g_vT_hi[(size_t)BATCH*HEADS*DHEAD*NTOK];
__device__ __nv_bfloat16 g_vT_lo[(size_t)BATCH*HEADS*DHEAD*NTOK];

// ---------------- PTX helpers (base sm_103-safe) ----------------------------
__device__ __forceinline__ uint32_t smem_u32(const void* p) {
    uint32_t a;
    asm("{ .reg .u64 t; cvta.to.shared.u64 t, %1; cvt.u32.u64 %0, t; }"
        : "=r"(a) : "l"(p));
    return a;
}
__device__ __forceinline__ void cp16(uint32_t dst, const void* src) {
    asm volatile("cp.async.cg.shared.global [%0], [%1], 16;"
                 :: "r"(dst), "l"(src) : "memory");
}
#define CP_COMMIT() asm volatile("cp.async.commit_group;" ::: "memory")
#define CP_WAIT1()  asm volatile("cp.async.wait_group 1;" ::: "memory")
#define CP_WAIT0()  asm volatile("cp.async.wait_group 0;" ::: "memory")

#define LDSM4(r0, r1, r2, r3, addr)                                            \
    asm volatile("ldmatrix.sync.aligned.m8n8.x4.shared.b16 {%0,%1,%2,%3}, [%4];" \
                 : "=r"(r0), "=r"(r1), "=r"(r2), "=r"(r3) : "r"(addr))

#define MMA16816(d, a, b)                                                      \
    asm volatile("mma.sync.aligned.m16n8k16.row.col.f32.bf16.bf16.f32 "        \
                 "{%0,%1,%2,%3}, {%4,%5,%6,%7}, {%8,%9}, {%0,%1,%2,%3};"       \
                 : "+f"((d)[0]), "+f"((d)[1]), "+f"((d)[2]), "+f"((d)[3])      \
                 : "r"((a)[0]), "r"((a)[1]), "r"((a)[2]), "r"((a)[3]),         \
                   "r"((b)[0]), "r"((b)[1]))

__device__ __forceinline__ void split2(float a, float b, uint32_t& hi, uint32_t& lo) {
    __nv_bfloat16 ha = __float2bfloat16(a), hb = __float2bfloat16(b);
    float ra = a - __bfloat162float(ha), rb = b - __bfloat162float(hb);
    __nv_bfloat16 la = __float2bfloat16(ra), lb = __float2bfloat16(rb);
    hi = ((uint32_t)__bfloat16_as_ushort(hb) << 16) | __bfloat16_as_ushort(ha);
    lo = ((uint32_t)__bfloat16_as_ushort(lb) << 16) | __bfloat16_as_ushort(la);
}

// ---------------------------------------------------------------------------
// bias (bf16): g_biasb[h][n][m] = bf16(bias_table[rel_index[n][m]][h])
// ---------------------------------------------------------------------------
__global__ void bias_kernel(const float* __restrict__ bias_table,
                            const int*   __restrict__ rel_index) {
    int idx = blockIdx.x * blockDim.x + threadIdx.x;
    if (idx >= NTOK * NTOK) return;
    int r = rel_index[idx];
#pragma unroll
    for (int h = 0; h < HEADS; h++)
        g_biasb[(size_t)h * NTOK * NTOK + idx] =
            __float2bfloat16(bias_table[r * HEADS + h]);
}

// ---------------------------------------------------------------------------
// split fp32 -> (hi, lo) bf16, same layout.
// ---------------------------------------------------------------------------
__global__ void split_kernel(const float* __restrict__ in,
                             __nv_bfloat16* __restrict__ hi,
                             __nv_bfloat16* __restrict__ lo, size_t n4) {
    size_t i = (size_t)blockIdx.x * blockDim.x + threadIdx.x;
    if (i >= n4) return;
    float4 v = ((const float4*)in)[i];
    float vv[4] = {v.x, v.y, v.z, v.w};
    uint32_t hp[2], lp[2];
    split2(vv[0], vv[1], hp[0], lp[0]);
    split2(vv[2], vv[3], hp[1], lp[1]);
    ((uint2*)hi)[i] = make_uint2(hp[0], hp[1]);
    ((uint2*)lo)[i] = make_uint2(lp[0], lp[1]);
}

// split + transpose weights: in [K,N] fp32 -> hiT/loT [N,K] bf16
__global__ void splitT_kernel(const float* __restrict__ in,
                              __nv_bfloat16* __restrict__ hiT,
                              __nv_bfloat16* __restrict__ loT, int K, int N) {
    int idx = blockIdx.x * blockDim.x + threadIdx.x;
    if (idx >= K * N) return;
    int n = idx / K, k = idx - n * K;
    float v = in[(size_t)k * N + n];
    __nv_bfloat16 h = __float2bfloat16(v);
    float r = v - __bfloat162float(h);
    hiT[idx] = h;
    loT[idx] = __float2bfloat16(r);
}

// ---------------------------------------------------------------------------
// QKV repack: g_qkv fp32 -> Q(scaled)/K packed [b,h,n,64] hi/lo; V transposed
// [b,h,64,n] hi/lo. Block = (64-row tile, h, b), 256 threads.
// ---------------------------------------------------------------------------
__global__ __launch_bounds__(256)
void splitqkv_kernel() {
    __shared__ __nv_bfloat16 th[64][80], tl[64][80];
    const int tile = blockIdx.x, h = blockIdx.y, b = blockIdx.z;
    const int bh = b * HEADS + h;
    const int tid = threadIdx.x;
    const int nl = tid >> 2, c4 = tid & 3;

    const float* base = g_qkv + ((size_t)(b * NTOK + tile * 64) + nl) * QKV3;

    // Q (scaled by 0.125) and K: straight split, coalesced writes
#pragma unroll
    for (int sec = 0; sec < 2; sec++) {
        const float* p = base + sec * INNER + h * DHEAD + c4 * 16;
        size_t o = ((size_t)bh * NTOK + tile * 64 + nl) * DHEAD + c4 * 16;
        __nv_bfloat16* oh = (sec ? g_k_hi : g_q_hi) + o;
        __nv_bfloat16* ol = (sec ? g_k_lo : g_q_lo) + o;
#pragma unroll
        for (int i = 0; i < 4; i++) {
            float4 v = *(const float4*)(p + i * 4);
            if (sec == 0) { v.x *= 0.125f; v.y *= 0.125f; v.z *= 0.125f; v.w *= 0.125f; }
            uint32_t h0, l0, h1, l1;
            split2(v.x, v.y, h0, l0);
            split2(v.z, v.w, h1, l1);
            *(uint2*)(oh + i * 4) = make_uint2(h0, h1);
            *(uint2*)(ol + i * 4) = make_uint2(l0, l1);
        }
    }

    // V: split into smem transposed, then coalesced writes
    {
        const float* p = base + 2 * INNER + h * DHEAD + c4 * 16;
#pragma unroll
        for (int i = 0; i < 4; i++) {
            float4 v = *(const float4*)(p + i * 4);
            float vv[4] = {v.x, v.y, v.z, v.w};
#pragma unroll
            for (int j = 0; j < 4; j++) {
                int d = c4 * 16 + i * 4 + j;
                __nv_bfloat16 hi = __float2bfloat16(vv[j]);
                th[d][nl] = hi;
                tl[d][nl] = __float2bfloat16(vv[j] - __bfloat162float(hi));
            }
        }
    }
    __syncthreads();
    {
        const int dl = tid >> 2, seg = tid & 3;
        size_t o = ((size_t)bh * DHEAD + dl) * NTOK + tile * 64 + seg * 16;
        *(uint4*)(g_vT_hi + o)     = *(uint4*)&th[dl][seg * 16];
        *(uint4*)(g_vT_hi + o + 8) = *(uint4*)&th[dl][seg * 16 + 8];
        *(uint4*)(g_vT_lo + o)     = *(uint4*)&tl[dl][seg * 16];
        *(uint4*)(g_vT_lo + o + 8) = *(uint4*)&tl[dl][seg * 16 + 8];
    }
}

// ---------------------------------------------------------------------------
// mma.sync bf16-split GEMM (unchanged from R5, proven)
// ---------------------------------------------------------------------------
#define STAGE_BYTES 32768
#define GSMEM_BYTES (3 * STAGE_BYTES)

template<bool ADD_B>
__global__ __launch_bounds__(256)
void gemm_mma(const __nv_bfloat16* __restrict__ Ahi, const __nv_bfloat16* __restrict__ Alo,
              const __nv_bfloat16* __restrict__ BThi, const __nv_bfloat16* __restrict__ BTlo,
              float* __restrict__ C, const float* __restrict__ bias, int Nn) {
    constexpr int K = 512;
    extern __shared__ char smem[];
    const int tid = threadIdx.x, wid = tid >> 5, lane = tid & 31;
    const int wm = wid >> 2, wn = wid & 3;
    const int bm = blockIdx.y * 128, bn = blockIdx.x * 128;
    const uint32_t sb = smem_u32(smem);

    const __nv_bfloat16* src0 = Ahi  + (size_t)bm * K;
    const __nv_bfloat16* src1 = Alo  + (size_t)bm * K;
    const __nv_bfloat16* src2 = BThi + (size_t)bn * K;
    const __nv_bfloat16* src3 = BTlo + (size_t)bn * K;

    auto issue = [&](int stage, int c) {
        const uint32_t d0 = sb + stage * STAGE_BYTES;
        const int k0 = c * BK;
        const __nv_bfloat16* srcs[4] = {src0, src1, src2, src3};
#pragma unroll
        for (int o = 0; o < 4; o++) {
#pragma unroll
            for (int i = 0; i < 2; i++) {
                int cid = tid + 256 * i;
                int row = cid >> 2, ch = cid & 3;
                int cc = ch ^ ((row >> 1) & 3);
                cp16(d0 + o * 8192 + row * 64 + cc * 16,
                     srcs[o] + (size_t)row * K + k0 + ch * 8);
            }
        }
    };

    float acc[4][4][4] = {};

    issue(0, 0); CP_COMMIT();
    issue(1, 1); CP_COMMIT();

    for (int c = 0; c < K / BK; c++) {
        const int s = c % 3;
        CP_WAIT1();
        __syncthreads();
        if (c + 2 < K / BK) issue((c + 2) % 3, c + 2);
        CP_COMMIT();

        const uint32_t stg = sb + s * STAGE_BYTES;
#pragma unroll
        for (int ks = 0; ks < 2; ks++) {
            uint32_t aH[4][4], aL[4][4], bH[4][2], bL[4][2];
#pragma unroll
            for (int mt = 0; mt < 4; mt++) {
                int row = wm * 64 + mt * 16 + (lane & 15);
                int ch = 2 * ks + (lane >> 4);
                int cc = ch ^ ((row >> 1) & 3);
                uint32_t ad = stg + row * 64 + cc * 16;
                LDSM4(aH[mt][0], aH[mt][1], aH[mt][2], aH[mt][3], ad);
                LDSM4(aL[mt][0], aL[mt][1], aL[mt][2], aL[mt][3], ad + 8192);
            }
#pragma unroll
            for (int np = 0; np < 2; np++) {
                int rown = wn * 32 + np * 16 + (lane & 7) + ((lane >> 4) << 3);
                int ch = 2 * ks + ((lane >> 3) & 1);
                int cc = ch ^ ((rown >> 1) & 3);
                uint32_t bd = stg + 16384 + rown * 64 + cc * 16;
                LDSM4(bH[2*np][0], bH[2*np][1], bH[2*np+1][0], bH[2*np+1][1], bd);
                LDSM4(bL[2*np][0], bL[2*np][1], bL[2*np+1][0], bL[2*np+1][1], bd + 8192);
            }
#pragma unroll
            for (int mt = 0; mt < 4; mt++)
#pragma unroll
                for (int nt = 0; nt < 4; nt++) {
                    MMA16816(acc[mt][nt], aH[mt], bH[nt]);
                    MMA16816(acc[mt][nt], aH[mt], bL[nt]);
                    MMA16816(acc[mt][nt], aL[mt], bH[nt]);
                }
        }
    }

#pragma unroll
    for (int mt = 0; mt < 4; mt++) {
        int row0 = bm + wm * 64 + mt * 16 + (lane >> 2);
#pragma unroll
        for (int nt = 0; nt < 4; nt++) {
            int col = bn + wn * 32 + nt * 8 + (lane & 3) * 2;
            float2 v0 = make_float2(acc[mt][nt][0], acc[mt][nt][1]);
            float2 v1 = make_float2(acc[mt][nt][2], acc[mt][nt][3]);
            if (ADD_B) {
                float b0 = bias[col], b1 = bias[col + 1];
                v0.x += b0; v0.y += b1; v1.x += b0; v1.y += b1;
            }
            *(float2*)&C[(size_t)row0 * Nn + col]       = v0;
            *(float2*)&C[(size_t)(row0 + 8) * Nn + col] = v1;
        }
    }
}

// ---------------------------------------------------------------------------
// Flash attention via mma.sync, split-bf16 both GEMMs.
// CTA = (128 Q rows, head, batch). 8 warps x 16 rows. KV chunks of 128.
// SMEM: Q hi/lo 32KB | K 2-stage 64KB | V 2-stage 64KB = 160KB.
// ---------------------------------------------------------------------------
#define ASMEM_Q  0
#define ASMEM_K  32768
#define ASMEM_V  98304
#define ASMEM_BYTES 163840

__global__ __launch_bounds__(256, 1)
void attn_mma() {
    extern __shared__ char smem[];
    const int tid = threadIdx.x, wid = tid >> 5, lane = tid & 31;
    const int qt = blockIdx.x, h = blockIdx.y, b = blockIdx.z;
    const int bh = b * HEADS + h;
    const uint32_t sb = smem_u32(smem);

    const __nv_bfloat16* Qh_g = g_q_hi + ((size_t)bh * NTOK + qt * 128) * DHEAD;
    const __nv_bfloat16* Ql_g = g_q_lo + ((size_t)bh * NTOK + qt * 128) * DHEAD;
    const __nv_bfloat16* Kh_g = g_k_hi + (size_t)bh * NTOK * DHEAD;
    const __nv_bfloat16* Kl_g = g_k_lo + (size_t)bh * NTOK * DHEAD;
    const __nv_bfloat16* Vh_g = g_vT_hi + (size_t)bh * DHEAD * NTOK;
    const __nv_bfloat16* Vl_g = g_vT_lo + (size_t)bh * DHEAD * NTOK;

    // ---- prologue: load Q tile (hi+lo) and KV chunk 0 ----
#pragma unroll
    for (int i = 0; i < 4; i++) {
        int cid = tid + 256 * i;
        int r = cid >> 3, c = cid & 7;
        uint32_t dst = sb + ASMEM_Q + r * 128 + ((c ^ (r & 7)) << 4);
        cp16(dst,          Qh_g + (size_t)r * DHEAD + c * 8);
        cp16(dst + 16384,  Ql_g + (size_t)r * DHEAD + c * 8);
    }
    CP_COMMIT();

    auto issueKV = [&](int t) {
        const int s = t & 1;
        uint32_t kbase = sb + ASMEM_K + s * 32768;
#pragma unroll
        for (int i = 0; i < 4; i++) {
            int cid = tid + 256 * i;
            int r = cid >> 3, c = cid & 7;
            uint32_t dst = kbase + r * 128 + ((c ^ (r & 7)) << 4);
            cp16(dst,         Kh_g + ((size_t)(t * 128 + r)) * DHEAD + c * 8);
            cp16(dst + 16384, Kl_g + ((size_t)(t * 128 + r)) * DHEAD + c * 8);
        }
        uint32_t vbase = sb + ASMEM_V + s * 32768;
#pragma unroll
        for (int i = 0; i < 4; i++) {
            int cid = tid + 256 * i;
            int d = cid >> 4, c = cid & 15;
            uint32_t dst = vbase + d * 256 + ((c ^ (d & 7)) << 4);
            cp16(dst,         Vh_g + (size_t)d * NTOK + t * 128 + c * 8);
            cp16(dst + 16384, Vl_g + (size_t)d * NTOK + t * 128 + c * 8);
        }
        CP_COMMIT();
    };
    issueKV(0);
    CP_WAIT0();
    __syncthreads();

    // ---- persistent Q fragments ----
    uint32_t aQh[4][4], aQl[4][4];
#pragma unroll
    for (int ks = 0; ks < 4; ks++) {
        int row = wid * 16 + (lane & 15);
        int c = 2 * ks + (lane >> 4);
        uint32_t ad = sb + ASMEM_Q + row * 128 + ((c ^ (row & 7)) << 4);
        LDSM4(aQh[ks][0], aQh[ks][1], aQh[ks][2], aQh[ks][3], ad);
        LDSM4(aQl[ks][0], aQl[ks][1], aQl[ks][2], aQl[ks][3], ad + 16384);
    }

    float O[8][4] = {};
    float m0 = -1e30f, m1 = -1e30f, l0 = 0.f, l1 = 0.f;
    const __nv_bfloat16* bias_row0 =
        g_biasb + (size_t)h * NTOK * NTOK + (size_t)(qt * 128 + wid * 16 + (lane >> 2)) * NTOK;

    for (int t = 0; t < NTOK / 128; t++) {
        if (t > 0) { CP_WAIT0(); __syncthreads(); }
        if (t + 1 < NTOK / 128) issueKV(t + 1);

        const uint32_t kb = sb + ASMEM_K + (t & 1) * 32768;
        const uint32_t vb = sb + ASMEM_V + (t & 1) * 32768;

        // ---- S = Q'K^T (split, 3 passes) ----
        float sc[16][4];
#pragma unroll
        for (int nt = 0; nt < 16; nt++) { sc[nt][0]=0.f; sc[nt][1]=0.f; sc[nt][2]=0.f; sc[nt][3]=0.f; }
#pragma unroll
        for (int ks = 0; ks < 4; ks++) {
#pragma unroll
            for (int np = 0; np < 8; np++) {
                int rowk = np * 16 + (lane & 7) + ((lane >> 4) << 3);
                int c = 2 * ks + ((lane >> 3) & 1);
                uint32_t ad = kb + rowk * 128 + ((c ^ (rowk & 7)) << 4);
                uint32_t kh[4], kl[4];
                LDSM4(kh[0], kh[1], kh[2], kh[3], ad);
                LDSM4(kl[0], kl[1], kl[2], kl[3], ad + 16384);
                uint32_t bh0[2] = {kh[0], kh[1]}, bh1[2] = {kh[2], kh[3]};
                uint32_t bl0[2] = {kl[0], kl[1]}, bl1[2] = {kl[2], kl[3]};
                MMA16816(sc[2*np],   aQh[ks], bh0);
                MMA16816(sc[2*np],   aQh[ks], bl0);
                MMA16816(sc[2*np],   aQl[ks], bh0);
                MMA16816(sc[2*np+1], aQh[ks], bh1);
                MMA16816(sc[2*np+1], aQh[ks], bl1);
                MMA16816(sc[2*np+1], aQl[ks], bh1);
            }
        }

        // ---- + bias ----
        {
            const __nv_bfloat16* bp0 = bias_row0 + t * 128 + 2 * (lane & 3);
            const __nv_bfloat16* bp1 = bp0 + 8 * NTOK;
#pragma unroll
            for (int nt = 0; nt < 16; nt++) {
                uint32_t u0 = *(const uint32_t*)(bp0 + nt * 8);
                uint32_t u1 = *(const uint32_t*)(bp1 + nt * 8);
                float2 f0 = __bfloat1622float2(*reinterpret_cast<__nv_bfloat162*>(&u0));
                float2 f1 = __bfloat1622float2(*reinterpret_cast<__nv_bfloat162*>(&u1));
                sc[nt][0] += f0.x; sc[nt][1] += f0.y;
                sc[nt][2] += f1.x; sc[nt][3] += f1.y;
            }
        }

        // ---- online softmax (row stats in lane quads) ----
        float mx0 = -1e30f, mx1 = -1e30f;
#pragma unroll
        for (int nt = 0; nt < 16; nt++) {
            mx0 = fmaxf(mx0, fmaxf(sc[nt][0], sc[nt][1]));
            mx1 = fmaxf(mx1, fmaxf(sc[nt][2], sc[nt][3]));
        }
        mx0 = fmaxf(mx0, __shfl_xor_sync(0xffffffffu, mx0, 1));
        mx0 = fmaxf(mx0, __shfl_xor_sync(0xffffffffu, mx0, 2));
        mx1 = fmaxf(mx1, __shfl_xor_sync(0xffffffffu, mx1, 1));
        mx1 = fmaxf(mx1, __shfl_xor_sync(0xffffffffu, mx1, 2));
        float nm0 = fmaxf(m0, mx0), nm1 = fmaxf(m1, mx1);
        float c0 = __expf(m0 - nm0), c1 = __expf(m1 - nm1);
        m0 = nm0; m1 = nm1;
        float rs0 = 0.f, rs1 = 0.f;
#pragma unroll
        for (int nt = 0; nt < 16; nt++) {
            sc[nt][0] = __expf(sc[nt][0] - m0); rs0 += sc[nt][0];
            sc[nt][1] = __expf(sc[nt][1] - m0); rs0 += sc[nt][1];
            sc[nt][2] = __expf(sc[nt][2] - m1); rs1 += sc[nt][2];
            sc[nt][3] = __expf(sc[nt][3] - m1); rs1 += sc[nt][3];
        }
        rs0 += __shfl_xor_sync(0xffffffffu, rs0, 1);
        rs0 += __shfl_xor_sync(0xffffffffu, rs0, 2);
        rs1 += __shfl_xor_sync(0xffffffffu, rs1, 1);
        rs1 += __shfl_xor_sync(0xffffffffu, rs1, 2);
        l0 = l0 * c0 + rs0;
        l1 = l1 * c1 + rs1;
#pragma unroll
        for (int dt = 0; dt < 8; dt++) {
            O[dt][0] *= c0; O[dt][1] *= c0; O[dt][2] *= c1; O[dt][3] *= c1;
        }

        // ---- O += P @ V (split, 3 passes; P frags from acc registers) ----
#pragma unroll
        for (int j = 0; j < 8; j++) {
            uint32_t aPh[4], aPl[4];
            split2(sc[2*j][0],   sc[2*j][1],   aPh[0], aPl[0]);
            split2(sc[2*j][2],   sc[2*j][3],   aPh[1], aPl[1]);
            split2(sc[2*j+1][0], sc[2*j+1][1], aPh[2], aPl[2]);
            split2(sc[2*j+1][2], sc[2*j+1][3], aPh[3], aPl[3]);
#pragma unroll
            for (int np = 0; np < 4; np++) {
                int rowd = np * 16 + (lane & 7) + ((lane >> 4) << 3);
                int c = 2 * j + ((lane >> 3) & 1);
                uint32_t ad = vb + rowd * 256 + ((c ^ (rowd & 7)) << 4);
                uint32_t vh[4], vl[4];
                LDSM4(vh[0], vh[1], vh[2], vh[3], ad);
                LDSM4(vl[0], vl[1], vl[2], vl[3], ad + 16384);
                uint32_t b0h[2] = {vh[0], vh[1]}, b1h[2] = {vh[2], vh[3]};
                uint32_t b0l[2] = {vl[0], vl[1]}, b1l[2] = {vl[2], vl[3]};
                MMA16816(O[2*np],   aPh, b0h);
                MMA16816(O[2*np],   aPh, b0l);
                MMA16816(O[2*np],   aPl, b0h);
                MMA16816(O[2*np+1], aPh, b1h);
                MMA16816(O[2*np+1], aPh, b1l);
                MMA16816(O[2*np+1], aPl, b1h);
            }
        }
    }

    // ---- normalize + split-store to g_att hi/lo ----
    float i0 = 1.f / l0, i1 = 1.f / l1;
    size_t r0 = (size_t)b * NTOK + qt * 128 + wid * 16 + (lane >> 2);
    int colo = h * DHEAD + 2 * (lane & 3);
#pragma unroll
    for (int dt = 0; dt < 8; dt++) {
        uint32_t h0, lo0, h1, lo1;
        split2(O[dt][0] * i0, O[dt][1] * i0, h0, lo0);
        split2(O[dt][2] * i1, O[dt][3] * i1, h1, lo1);
        *(uint32_t*)(g_att_hi + r0 * INNER + colo + dt * 8)       = h0;
        *(uint32_t*)(g_att_lo + r0 * INNER + colo + dt * 8)       = lo0;
        *(uint32_t*)(g_att_hi + (r0 + 8) * INNER + colo + dt * 8) = h1;
        *(uint32_t*)(g_att_lo + (r0 + 8) * INNER + colo + dt * 8) = lo1;
    }
}

// ---------------------------------------------------------------------------
extern "C" void kernel_launch(void* const* d_in, const int* in_sizes, int n_in,
                              void* d_out, int out_size) {
    const float* x          = (const float*)d_in[0];
    const float* w_qkv      = (const float*)d_in[1];
    const float* w_out      = (const float*)d_in[2];
    const float* b_out      = (const float*)d_in[3];
    const float* bias_table = (const float*)d_in[4];
    const int*   rel_index  = (const int*)  d_in[5];
    float* out = (float*)d_out;

    float* qkv;
    __nv_bfloat16 *xh, *xl, *ah, *al, *wqh, *wql, *woh, *wol;
    cudaGetSymbolAddress((void**)&qkv, g_qkv);
    cudaGetSymbolAddress((void**)&xh,  g_x_hi);
    cudaGetSymbolAddress((void**)&xl,  g_x_lo);
    cudaGetSymbolAddress((void**)&ah,  g_att_hi);
    cudaGetSymbolAddress((void**)&al,  g_att_lo);
    cudaGetSymbolAddress((void**)&wqh, g_wqkvT_hi);
    cudaGetSymbolAddress((void**)&wql, g_wqkvT_lo);
    cudaGetSymbolAddress((void**)&woh, g_woutT_hi);
    cudaGetSymbolAddress((void**)&wol, g_woutT_lo);

    cudaFuncSetAttribute(gemm_mma<false>, cudaFuncAttributeMaxDynamicSharedMemorySize, GSMEM_BYTES);
    cudaFuncSetAttribute(gemm_mma<true>,  cudaFuncAttributeMaxDynamicSharedMemorySize, GSMEM_BYTES);
    cudaFuncSetAttribute(attn_mma, cudaFuncAttributeMaxDynamicSharedMemorySize, ASMEM_BYTES);

    // 1) bias expansion (bf16)
    bias_kernel<<<(NTOK * NTOK + 255) / 256, 256>>>(bias_table, rel_index);

    // 2) split x and w_qkv
    {
        size_t n4 = (size_t)MROWS * INNER / 4;
        split_kernel<<<(unsigned)((n4 + 255) / 256), 256>>>(x, xh, xl, n4);
        int nw = INNER * QKV3;
        splitT_kernel<<<(nw + 255) / 256, 256>>>(w_qkv, wqh, wql, INNER, QKV3);
    }

    // 3) qkv = x @ w_qkv
    gemm_mma<false><<<dim3(QKV3 / 128, MROWS / 128), 256, GSMEM_BYTES>>>(
        xh, xl, wqh, wql, qkv, nullptr, QKV3);

    // 4) repack qkv -> Q/K packed + V transposed, split bf16
    splitqkv_kernel<<<dim3(NTOK / 64, HEADS, BATCH), 256>>>();

    // 5) flash attention (mma.sync) -> writes g_att hi/lo directly
    attn_mma<<<dim3(NTOK / 128, HEADS, BATCH), 256, ASMEM_BYTES>>>();

    // 6) out = att @ w_out + b_out
    {
        int nw = INNER * INNER;
        splitT_kernel<<<(nw + 255) / 256, 256>>>(w_out, woh, wol, INNER, INNER);
    }
    gemm_mma<true><<<dim3(INNER / 128, MROWS / 128), 256, GSMEM_BYTES>>>(
        ah, al, woh, wol, out, b_out, INNER);
}

// round 7
// speedup vs baseline: 3.2986x; 1.1223x over previous
#include <cuda_runtime.h>
#include <cuda_bf16.h>
#include <cstdint>
#include <cstddef>

#define NTOK   1024
#define BATCH  32
#define HEADS  8
#define DHEAD  64
#define INNER  512
#define QKV3   (3*INNER)
#define MROWS  (BATCH*NTOK)
#define BK     32

// ---------------- scratch (static device globals; no allocation allowed) ----
__device__ __nv_bfloat16 g_biasb[(size_t)HEADS*NTOK*NTOK]; // bias (bf16)

__device__ __nv_bfloat16 g_x_hi  [(size_t)MROWS*INNER];
__device__ __nv_bfloat16 g_x_lo  [(size_t)MROWS*INNER];
__device__ __nv_bfloat16 g_att_hi[(size_t)MROWS*INNER];
__device__ __nv_bfloat16 g_att_lo[(size_t)MROWS*INNER];
__device__ __nv_bfloat16 g_wqkvT_hi[(size_t)QKV3*INNER];
__device__ __nv_bfloat16 g_wqkvT_lo[(size_t)QKV3*INNER];
__device__ __nv_bfloat16 g_woutT_hi[(size_t)INNER*INNER];
__device__ __nv_bfloat16 g_woutT_lo[(size_t)INNER*INNER];

// attention operands: Q,K packed [b,h,n,64]; V transposed [b,h,64,n]
__device__ __nv_bfloat16 g_q_hi [(size_t)BATCH*HEADS*NTOK*DHEAD];
__device__ __nv_bfloat16 g_q_lo [(size_t)BATCH*HEADS*NTOK*DHEAD];
__device__ __nv_bfloat16 g_k_hi [(size_t)BATCH*HEADS*NTOK*DHEAD];
__device__ __nv_bfloat16 g_k_lo [(size_t)BATCH*HEADS*NTOK*DHEAD];
__device__ __nv_bfloat16 g_vT_hi[(size_t)BATCH*HEADS*DHEAD*NTOK];
__device__ __nv_bfloat16 g_vT_lo[(size_t)BATCH*HEADS*DHEAD*NTOK];

// ---------------- PTX helpers (base sm_103-safe) ----------------------------
__device__ __forceinline__ uint32_t smem_u32(const void* p) {
    uint32_t a;
    asm("{ .reg .u64 t; cvta.to.shared.u64 t, %1; cvt.u32.u64 %0, t; }"
        : "=r"(a) : "l"(p));
    return a;
}
__device__ __forceinline__ void cp16(uint32_t dst, const void* src) {
    asm volatile("cp.async.cg.shared.global [%0], [%1], 16;"
                 :: "r"(dst), "l"(src) : "memory");
}
#define CP_COMMIT() asm volatile("cp.async.commit_group;" ::: "memory")
#define CP_WAIT1()  asm volatile("cp.async.wait_group 1;" ::: "memory")
#define CP_WAIT0()  asm volatile("cp.async.wait_group 0;" ::: "memory")

#define LDSM4(r0, r1, r2, r3, addr)                                            \
    asm volatile("ldmatrix.sync.aligned.m8n8.x4.shared.b16 {%0,%1,%2,%3}, [%4];" \
                 : "=r"(r0), "=r"(r1), "=r"(r2), "=r"(r3) : "r"(addr))

#define MMA16816(d, a, b)                                                      \
    asm volatile("mma.sync.aligned.m16n8k16.row.col.f32.bf16.bf16.f32 "        \
                 "{%0,%1,%2,%3}, {%4,%5,%6,%7}, {%8,%9}, {%0,%1,%2,%3};"       \
                 : "+f"((d)[0]), "+f"((d)[1]), "+f"((d)[2]), "+f"((d)[3])      \
                 : "r"((a)[0]), "r"((a)[1]), "r"((a)[2]), "r"((a)[3]),         \
                   "r"((b)[0]), "r"((b)[1]))

__device__ __forceinline__ void split2(float a, float b, uint32_t& hi, uint32_t& lo) {
    __nv_bfloat16 ha = __float2bfloat16(a), hb = __float2bfloat16(b);
    float ra = a - __bfloat162float(ha), rb = b - __bfloat162float(hb);
    __nv_bfloat16 la = __float2bfloat16(ra), lb = __float2bfloat16(rb);
    hi = ((uint32_t)__bfloat16_as_ushort(hb) << 16) | __bfloat16_as_ushort(ha);
    lo = ((uint32_t)__bfloat16_as_ushort(lb) << 16) | __bfloat16_as_ushort(la);
}

// ---------------------------------------------------------------------------
// bias (bf16): g_biasb[h][n][m] = bf16(bias_table[rel_index[n][m]][h])
// ---------------------------------------------------------------------------
__global__ void bias_kernel(const float* __restrict__ bias_table,
                            const int*   __restrict__ rel_index) {
    int idx = blockIdx.x * blockDim.x + threadIdx.x;
    if (idx >= NTOK * NTOK) return;
    int r = rel_index[idx];
#pragma unroll
    for (int h = 0; h < HEADS; h++)
        g_biasb[(size_t)h * NTOK * NTOK + idx] =
            __float2bfloat16(bias_table[r * HEADS + h]);
}

// ---------------------------------------------------------------------------
// split fp32 -> (hi, lo) bf16, same layout.
// ---------------------------------------------------------------------------
__global__ void split_kernel(const float* __restrict__ in,
                             __nv_bfloat16* __restrict__ hi,
                             __nv_bfloat16* __restrict__ lo, size_t n4) {
    size_t i = (size_t)blockIdx.x * blockDim.x + threadIdx.x;
    if (i >= n4) return;
    float4 v = ((const float4*)in)[i];
    uint32_t hp[2], lp[2];
    split2(v.x, v.y, hp[0], lp[0]);
    split2(v.z, v.w, hp[1], lp[1]);
    ((uint2*)hi)[i] = make_uint2(hp[0], hp[1]);
    ((uint2*)lo)[i] = make_uint2(lp[0], lp[1]);
}

// split + transpose weights: in [K,N] fp32 -> hiT/loT [N,K] bf16
__global__ void splitT_kernel(const float* __restrict__ in,
                              __nv_bfloat16* __restrict__ hiT,
                              __nv_bfloat16* __restrict__ loT, int K, int N) {
    int idx = blockIdx.x * blockDim.x + threadIdx.x;
    if (idx >= K * N) return;
    int n = idx / K, k = idx - n * K;
    float v = in[(size_t)k * N + n];
    __nv_bfloat16 h = __float2bfloat16(v);
    float r = v - __bfloat162float(h);
    hiT[idx] = h;
    loT[idx] = __float2bfloat16(r);
}

// ---------------------------------------------------------------------------
// Shared GEMM mainloop (macro-free inline): computes acc[4][4][4] for a
// 128x128 tile of (Ahi+Alo) @ (Bhi+Blo)^T with K=512, 3-stage cp.async.
// ---------------------------------------------------------------------------
#define STAGE_BYTES 32768
#define GSMEM_BYTES (3 * STAGE_BYTES)

__device__ __forceinline__ void gemm_mainloop(
    const __nv_bfloat16* src0, const __nv_bfloat16* src1,
    const __nv_bfloat16* src2, const __nv_bfloat16* src3,
    uint32_t sb, int tid, int wm, int wn, int lane, float acc[4][4][4]) {
    constexpr int K = 512;

    auto issue = [&](int stage, int c) {
        const uint32_t d0 = sb + stage * STAGE_BYTES;
        const int k0 = c * BK;
        const __nv_bfloat16* srcs[4] = {src0, src1, src2, src3};
#pragma unroll
        for (int o = 0; o < 4; o++) {
#pragma unroll
            for (int i = 0; i < 2; i++) {
                int cid = tid + 256 * i;
                int row = cid >> 2, ch = cid & 3;
                int cc = ch ^ ((row >> 1) & 3);
                cp16(d0 + o * 8192 + row * 64 + cc * 16,
                     srcs[o] + (size_t)row * K + k0 + ch * 8);
            }
        }
    };

    issue(0, 0); CP_COMMIT();
    issue(1, 1); CP_COMMIT();

    for (int c = 0; c < K / BK; c++) {
        const int s = c % 3;
        CP_WAIT1();
        __syncthreads();
        if (c + 2 < K / BK) issue((c + 2) % 3, c + 2);
        CP_COMMIT();

        const uint32_t stg = sb + s * STAGE_BYTES;
#pragma unroll
        for (int ks = 0; ks < 2; ks++) {
            uint32_t aH[4][4], aL[4][4], bH[4][2], bL[4][2];
#pragma unroll
            for (int mt = 0; mt < 4; mt++) {
                int row = wm * 64 + mt * 16 + (lane & 15);
                int ch = 2 * ks + (lane >> 4);
                int cc = ch ^ ((row >> 1) & 3);
                uint32_t ad = stg + row * 64 + cc * 16;
                LDSM4(aH[mt][0], aH[mt][1], aH[mt][2], aH[mt][3], ad);
                LDSM4(aL[mt][0], aL[mt][1], aL[mt][2], aL[mt][3], ad + 8192);
            }
#pragma unroll
            for (int np = 0; np < 2; np++) {
                int rown = wn * 32 + np * 16 + (lane & 7) + ((lane >> 4) << 3);
                int ch = 2 * ks + ((lane >> 3) & 1);
                int cc = ch ^ ((rown >> 1) & 3);
                uint32_t bd = stg + 16384 + rown * 64 + cc * 16;
                LDSM4(bH[2*np][0], bH[2*np][1], bH[2*np+1][0], bH[2*np+1][1], bd);
                LDSM4(bL[2*np][0], bL[2*np][1], bL[2*np+1][0], bL[2*np+1][1], bd + 8192);
            }
#pragma unroll
            for (int mt = 0; mt < 4; mt++)
#pragma unroll
                for (int nt = 0; nt < 4; nt++) {
                    MMA16816(acc[mt][nt], aH[mt], bH[nt]);
                    MMA16816(acc[mt][nt], aH[mt], bL[nt]);
                    MMA16816(acc[mt][nt], aL[mt], bH[nt]);
                }
        }
    }
}

// ---------------------------------------------------------------------------
// QKV GEMM with fused split/repack epilogue:
//   section Q (bn<512):  scale 0.125, split -> g_q_hi/lo [bh,tok,64]
//   section K:           split -> g_k_hi/lo [bh,tok,64]
//   section V:           split + transpose via smem -> g_vT_hi/lo [bh,d,tok]
// ---------------------------------------------------------------------------
__global__ __launch_bounds__(256)
void gemm_qkv() {
    extern __shared__ char smem[];
    const int tid = threadIdx.x, wid = tid >> 5, lane = tid & 31;
    const int wm = wid >> 2, wn = wid & 3;
    const int bm = blockIdx.y * 128;
    const int sec = blockIdx.x >> 2;        // 0=Q 1=K 2=V
    const int cb  = blockIdx.x & 3;         // 128-col block within section
    const uint32_t sb = smem_u32(smem);

    constexpr int K = 512;
    float acc[4][4][4] = {};
    gemm_mainloop(g_x_hi + (size_t)bm * K, g_x_lo + (size_t)bm * K,
                  g_wqkvT_hi + (size_t)(sec * 512 + cb * 128) * K,
                  g_wqkvT_lo + (size_t)(sec * 512 + cb * 128) * K,
                  sb, tid, wm, wn, lane, acc);

    const int b = bm >> 10, tokb = bm & 1023;

    if (sec < 2) {
        // Q or K: packed [bh, tok, 64] writes (d even => 4B aligned)
        __nv_bfloat16* oh = sec ? g_k_hi : g_q_hi;
        __nv_bfloat16* ol = sec ? g_k_lo : g_q_lo;
        const float s = sec ? 1.0f : 0.125f;
#pragma unroll
        for (int mt = 0; mt < 4; mt++) {
            int tok = tokb + wm * 64 + mt * 16 + (lane >> 2);
#pragma unroll
            for (int nt = 0; nt < 4; nt++) {
                int col = cb * 128 + wn * 32 + nt * 8 + (lane & 3) * 2;
                int h = col >> 6, d = col & 63;
                size_t o0 = (((size_t)(b * HEADS + h)) * NTOK + tok) * DHEAD + d;
                uint32_t h0, l0, h1, l1;
                split2(acc[mt][nt][0] * s, acc[mt][nt][1] * s, h0, l0);
                split2(acc[mt][nt][2] * s, acc[mt][nt][3] * s, h1, l1);
                *(uint32_t*)(oh + o0)              = h0;
                *(uint32_t*)(ol + o0)              = l0;
                *(uint32_t*)(oh + o0 + 8 * DHEAD)  = h1;
                *(uint32_t*)(ol + o0 + 8 * DHEAD)  = l1;
            }
        }
    } else {
        // V: stage split bf16 transposed in smem, then coalesced writes
        __syncthreads();   // mainloop smem stages are dead now
        __nv_bfloat16* sh = (__nv_bfloat16*)smem;          // [128][136]
        __nv_bfloat16* sl = sh + 128 * 136;
#pragma unroll
        for (int mt = 0; mt < 4; mt++) {
            int r = wm * 64 + mt * 16 + (lane >> 2);
#pragma unroll
            for (int nt = 0; nt < 4; nt++) {
                int c = wn * 32 + nt * 8 + (lane & 3) * 2;
#pragma unroll
                for (int half = 0; half < 2; half++) {
                    float v0 = acc[mt][nt][2 * half + 0];
                    float v1 = acc[mt][nt][2 * half + 1];
                    int rr = r + half * 8;
                    __nv_bfloat16 b0 = __float2bfloat16(v0);
                    __nv_bfloat16 b1 = __float2bfloat16(v1);
                    sh[c * 136 + rr]       = b0;
                    sh[(c + 1) * 136 + rr] = b1;
                    sl[c * 136 + rr]       = __float2bfloat16(v0 - __bfloat162float(b0));
                    sl[(c + 1) * 136 + rr] = __float2bfloat16(v1 - __bfloat162float(b1));
                }
            }
        }
        __syncthreads();
        {
            int dl = tid >> 1, seg = (tid & 1) * 64;   // dl: 0..127 (2 heads x 64)
            int h = cb * 2 + (dl >> 6), d = dl & 63;
            size_t o = (((size_t)(b * HEADS + h)) * DHEAD + d) * NTOK + tokb + seg;
#pragma unroll
            for (int j = 0; j < 8; j++) {
                *(uint4*)(g_vT_hi + o + j * 8) = *(uint4*)(sh + dl * 136 + seg + j * 8);
                *(uint4*)(g_vT_lo + o + j * 8) = *(uint4*)(sl + dl * 136 + seg + j * 8);
            }
        }
    }
}

// ---------------------------------------------------------------------------
// Output-projection GEMM (att hi/lo @ woutT + b_out) -> fp32 out
// ---------------------------------------------------------------------------
__global__ __launch_bounds__(256)
void gemm_out(float* __restrict__ C, const float* __restrict__ bias) {
    extern __shared__ char smem[];
    const int tid = threadIdx.x, wid = tid >> 5, lane = tid & 31;
    const int wm = wid >> 2, wn = wid & 3;
    const int bm = blockIdx.y * 128, bn = blockIdx.x * 128;
    const uint32_t sb = smem_u32(smem);

    constexpr int K = 512;
    float acc[4][4][4] = {};
    gemm_mainloop(g_att_hi + (size_t)bm * K, g_att_lo + (size_t)bm * K,
                  g_woutT_hi + (size_t)bn * K, g_woutT_lo + (size_t)bn * K,
                  sb, tid, wm, wn, lane, acc);

#pragma unroll
    for (int mt = 0; mt < 4; mt++) {
        int row0 = bm + wm * 64 + mt * 16 + (lane >> 2);
#pragma unroll
        for (int nt = 0; nt < 4; nt++) {
            int col = bn + wn * 32 + nt * 8 + (lane & 3) * 2;
            float b0 = bias[col], b1 = bias[col + 1];
            float2 v0 = make_float2(acc[mt][nt][0] + b0, acc[mt][nt][1] + b1);
            float2 v1 = make_float2(acc[mt][nt][2] + b0, acc[mt][nt][3] + b1);
            *(float2*)&C[(size_t)row0 * INNER + col]       = v0;
            *(float2*)&C[(size_t)(row0 + 8) * INNER + col] = v1;
        }
    }
}

// ---------------------------------------------------------------------------
// Flash attention via mma.sync, split-bf16 both GEMMs (unchanged from R6).
// ---------------------------------------------------------------------------
#define ASMEM_Q  0
#define ASMEM_K  32768
#define ASMEM_V  98304
#define ASMEM_BYTES 163840

__global__ __launch_bounds__(256, 1)
void attn_mma() {
    extern __shared__ char smem[];
    const int tid = threadIdx.x, wid = tid >> 5, lane = tid & 31;
    const int qt = blockIdx.x, h = blockIdx.y, b = blockIdx.z;
    const int bh = b * HEADS + h;
    const uint32_t sb = smem_u32(smem);

    const __nv_bfloat16* Qh_g = g_q_hi + ((size_t)bh * NTOK + qt * 128) * DHEAD;
    const __nv_bfloat16* Ql_g = g_q_lo + ((size_t)bh * NTOK + qt * 128) * DHEAD;
    const __nv_bfloat16* Kh_g = g_k_hi + (size_t)bh * NTOK * DHEAD;
    const __nv_bfloat16* Kl_g = g_k_lo + (size_t)bh * NTOK * DHEAD;
    const __nv_bfloat16* Vh_g = g_vT_hi + (size_t)bh * DHEAD * NTOK;
    const __nv_bfloat16* Vl_g = g_vT_lo + (size_t)bh * DHEAD * NTOK;

#pragma unroll
    for (int i = 0; i < 4; i++) {
        int cid = tid + 256 * i;
        int r = cid >> 3, c = cid & 7;
        uint32_t dst = sb + ASMEM_Q + r * 128 + ((c ^ (r & 7)) << 4);
        cp16(dst,          Qh_g + (size_t)r * DHEAD + c * 8);
        cp16(dst + 16384,  Ql_g + (size_t)r * DHEAD + c * 8);
    }
    CP_COMMIT();

    auto issueKV = [&](int t) {
        const int s = t & 1;
        uint32_t kbase = sb + ASMEM_K + s * 32768;
#pragma unroll
        for (int i = 0; i < 4; i++) {
            int cid = tid + 256 * i;
            int r = cid >> 3, c = cid & 7;
            uint32_t dst = kbase + r * 128 + ((c ^ (r & 7)) << 4);
            cp16(dst,         Kh_g + ((size_t)(t * 128 + r)) * DHEAD + c * 8);
            cp16(dst + 16384, Kl_g + ((size_t)(t * 128 + r)) * DHEAD + c * 8);
        }
        uint32_t vbase = sb + ASMEM_V + s * 32768;
#pragma unroll
        for (int i = 0; i < 4; i++) {
            int cid = tid + 256 * i;
            int d = cid >> 4, c = cid & 15;
            uint32_t dst = vbase + d * 256 + ((c ^ (d & 7)) << 4);
            cp16(dst,         Vh_g + (size_t)d * NTOK + t * 128 + c * 8);
            cp16(dst + 16384, Vl_g + (size_t)d * NTOK + t * 128 + c * 8);
        }
        CP_COMMIT();
    };
    issueKV(0);
    CP_WAIT0();
    __syncthreads();

    uint32_t aQh[4][4], aQl[4][4];
#pragma unroll
    for (int ks = 0; ks < 4; ks++) {
        int row = wid * 16 + (lane & 15);
        int c = 2 * ks + (lane >> 4);
        uint32_t ad = sb + ASMEM_Q + row * 128 + ((c ^ (row & 7)) << 4);
        LDSM4(aQh[ks][0], aQh[ks][1], aQh[ks][2], aQh[ks][3], ad);
        LDSM4(aQl[ks][0], aQl[ks][1], aQl[ks][2], aQl[ks][3], ad + 16384);
    }

    float O[8][4] = {};
    float m0 = -1e30f, m1 = -1e30f, l0 = 0.f, l1 = 0.f;
    const __nv_bfloat16* bias_row0 =
        g_biasb + (size_t)h * NTOK * NTOK + (size_t)(qt * 128 + wid * 16 + (lane >> 2)) * NTOK;

    for (int t = 0; t < NTOK / 128; t++) {
        if (t > 0) { CP_WAIT0(); __syncthreads(); }
        if (t + 1 < NTOK / 128) issueKV(t + 1);

        const uint32_t kb = sb + ASMEM_K + (t & 1) * 32768;
        const uint32_t vb = sb + ASMEM_V + (t & 1) * 32768;

        float sc[16][4];
#pragma unroll
        for (int nt = 0; nt < 16; nt++) { sc[nt][0]=0.f; sc[nt][1]=0.f; sc[nt][2]=0.f; sc[nt][3]=0.f; }
#pragma unroll
        for (int ks = 0; ks < 4; ks++) {
#pragma unroll
            for (int np = 0; np < 8; np++) {
                int rowk = np * 16 + (lane & 7) + ((lane >> 4) << 3);
                int c = 2 * ks + ((lane >> 3) & 1);
                uint32_t ad = kb + rowk * 128 + ((c ^ (rowk & 7)) << 4);
                uint32_t kh[4], kl[4];
                LDSM4(kh[0], kh[1], kh[2], kh[3], ad);
                LDSM4(kl[0], kl[1], kl[2], kl[3], ad + 16384);
                uint32_t bh0[2] = {kh[0], kh[1]}, bh1[2] = {kh[2], kh[3]};
                uint32_t bl0[2] = {kl[0], kl[1]}, bl1[2] = {kl[2], kl[3]};
                MMA16816(sc[2*np],   aQh[ks], bh0);
                MMA16816(sc[2*np],   aQh[ks], bl0);
                MMA16816(sc[2*np],   aQl[ks], bh0);
                MMA16816(sc[2*np+1], aQh[ks], bh1);
                MMA16816(sc[2*np+1], aQh[ks], bl1);
                MMA16816(sc[2*np+1], aQl[ks], bh1);
            }
        }

        {
            const __nv_bfloat16* bp0 = bias_row0 + t * 128 + 2 * (lane & 3);
            const __nv_bfloat16* bp1 = bp0 + 8 * NTOK;
#pragma unroll
            for (int nt = 0; nt < 16; nt++) {
                uint32_t u0 = *(const uint32_t*)(bp0 + nt * 8);
                uint32_t u1 = *(const uint32_t*)(bp1 + nt * 8);
                float2 f0 = __bfloat1622float2(*reinterpret_cast<__nv_bfloat162*>(&u0));
                float2 f1 = __bfloat1622float2(*reinterpret_cast<__nv_bfloat162*>(&u1));
                sc[nt][0] += f0.x; sc[nt][1] += f0.y;
                sc[nt][2] += f1.x; sc[nt][3] += f1.y;
            }
        }

        float mx0 = -1e30f, mx1 = -1e30f;
#pragma unroll
        for (int nt = 0; nt < 16; nt++) {
            mx0 = fmaxf(mx0, fmaxf(sc[nt][0], sc[nt][1]));
            mx1 = fmaxf(mx1, fmaxf(sc[nt][2], sc[nt][3]));
        }
        mx0 = fmaxf(mx0, __shfl_xor_sync(0xffffffffu, mx0, 1));
        mx0 = fmaxf(mx0, __shfl_xor_sync(0xffffffffu, mx0, 2));
        mx1 = fmaxf(mx1, __shfl_xor_sync(0xffffffffu, mx1, 1));
        mx1 = fmaxf(mx1, __shfl_xor_sync(0xffffffffu, mx1, 2));
        float nm0 = fmaxf(m0, mx0), nm1 = fmaxf(m1, mx1);
        float c0 = __expf(m0 - nm0), c1 = __expf(m1 - nm1);
        m0 = nm0; m1 = nm1;
        float rs0 = 0.f, rs1 = 0.f;
#pragma unroll
        for (int nt = 0; nt < 16; nt++) {
            sc[nt][0] = __expf(sc[nt][0] - m0); rs0 += sc[nt][0];
            sc[nt][1] = __expf(sc[nt][1] - m0); rs0 += sc[nt][1];
            sc[nt][2] = __expf(sc[nt][2] - m1); rs1 += sc[nt][2];
            sc[nt][3] = __expf(sc[nt][3] - m1); rs1 += sc[nt][3];
        }
        rs0 += __shfl_xor_sync(0xffffffffu, rs0, 1);
        rs0 += __shfl_xor_sync(0xffffffffu, rs0, 2);
        rs1 += __shfl_xor_sync(0xffffffffu, rs1, 1);
        rs1 += __shfl_xor_sync(0xffffffffu, rs1, 2);
        l0 = l0 * c0 + rs0;
        l1 = l1 * c1 + rs1;
#pragma unroll
        for (int dt = 0; dt < 8; dt++) {
            O[dt][0] *= c0; O[dt][1] *= c0; O[dt][2] *= c1; O[dt][3] *= c1;
        }

#pragma unroll
        for (int j = 0; j < 8; j++) {
            uint32_t aPh[4], aPl[4];
            split2(sc[2*j][0],   sc[2*j][1],   aPh[0], aPl[0]);
            split2(sc[2*j][2],   sc[2*j][3],   aPh[1], aPl[1]);
            split2(sc[2*j+1][0], sc[2*j+1][1], aPh[2], aPl[2]);
            split2(sc[2*j+1][2], sc[2*j+1][3], aPh[3], aPl[3]);
#pragma unroll
            for (int np = 0; np < 4; np++) {
                int rowd = np * 16 + (lane & 7) + ((lane >> 4) << 3);
                int c = 2 * j + ((lane >> 3) & 1);
                uint32_t ad = vb + rowd * 256 + ((c ^ (rowd & 7)) << 4);
                uint32_t vh[4], vl[4];
                LDSM4(vh[0], vh[1], vh[2], vh[3], ad);
                LDSM4(vl[0], vl[1], vl[2], vl[3], ad + 16384);
                uint32_t b0h[2] = {vh[0], vh[1]}, b1h[2] = {vh[2], vh[3]};
                uint32_t b0l[2] = {vl[0], vl[1]}, b1l[2] = {vl[2], vl[3]};
                MMA16816(O[2*np],   aPh, b0h);
                MMA16816(O[2*np],   aPh, b0l);
                MMA16816(O[2*np],   aPl, b0h);
                MMA16816(O[2*np+1], aPh, b1h);
                MMA16816(O[2*np+1], aPh, b1l);
                MMA16816(O[2*np+1], aPl, b1h);
            }
        }
    }

    float i0 = 1.f / l0, i1 = 1.f / l1;
    size_t r0 = (size_t)b * NTOK + qt * 128 + wid * 16 + (lane >> 2);
    int colo = h * DHEAD + 2 * (lane & 3);
#pragma unroll
    for (int dt = 0; dt < 8; dt++) {
        uint32_t h0, lo0, h1, lo1;
        split2(O[dt][0] * i0, O[dt][1] * i0, h0, lo0);
        split2(O[dt][2] * i1, O[dt][3] * i1, h1, lo1);
        *(uint32_t*)(g_att_hi + r0 * INNER + colo + dt * 8)       = h0;
        *(uint32_t*)(g_att_lo + r0 * INNER + colo + dt * 8)       = lo0;
        *(uint32_t*)(g_att_hi + (r0 + 8) * INNER + colo + dt * 8) = h1;
        *(uint32_t*)(g_att_lo + (r0 + 8) * INNER + colo + dt * 8) = lo1;
    }
}

// ---------------------------------------------------------------------------
extern "C" void kernel_launch(void* const* d_in, const int* in_sizes, int n_in,
                              void* d_out, int out_size) {
    const float* x          = (const float*)d_in[0];
    const float* w_qkv      = (const float*)d_in[1];
    const float* w_out      = (const float*)d_in[2];
    const float* b_out      = (const float*)d_in[3];
    const float* bias_table = (const float*)d_in[4];
    const int*   rel_index  = (const int*)  d_in[5];
    float* out = (float*)d_out;

    __nv_bfloat16 *xh, *xl, *wqh, *wql, *woh, *wol;
    cudaGetSymbolAddress((void**)&xh,  g_x_hi);
    cudaGetSymbolAddress((void**)&xl,  g_x_lo);
    cudaGetSymbolAddress((void**)&wqh, g_wqkvT_hi);
    cudaGetSymbolAddress((void**)&wql, g_wqkvT_lo);
    cudaGetSymbolAddress((void**)&woh, g_woutT_hi);
    cudaGetSymbolAddress((void**)&wol, g_woutT_lo);

    cudaFuncSetAttribute(gemm_qkv, cudaFuncAttributeMaxDynamicSharedMemorySize, GSMEM_BYTES);
    cudaFuncSetAttribute(gemm_out, cudaFuncAttributeMaxDynamicSharedMemorySize, GSMEM_BYTES);
    cudaFuncSetAttribute(attn_mma, cudaFuncAttributeMaxDynamicSharedMemorySize, ASMEM_BYTES);

    // 1) prep: bias expansion, input split, weight split-transposes
    bias_kernel<<<(NTOK * NTOK + 255) / 256, 256>>>(bias_table, rel_index);
    {
        size_t n4 = (size_t)MROWS * INNER / 4;
        split_kernel<<<(unsigned)((n4 + 255) / 256), 256>>>(x, xh, xl, n4);
        splitT_kernel<<<(INNER * QKV3 + 255) / 256, 256>>>(w_qkv, wqh, wql, INNER, QKV3);
        splitT_kernel<<<(INNER * INNER + 255) / 256, 256>>>(w_out, woh, wol, INNER, INNER);
    }

    // 2) QKV GEMM with fused split/repack epilogue
    gemm_qkv<<<dim3(QKV3 / 128, MROWS / 128), 256, GSMEM_BYTES>>>();

    // 3) flash attention (mma.sync) -> writes g_att hi/lo directly
    attn_mma<<<dim3(NTOK / 128, HEADS, BATCH), 256, ASMEM_BYTES>>>();

    // 4) out = att @ w_out + b_out
    gemm_out<<<dim3(INNER / 128, MROWS / 128), 256, GSMEM_BYTES>>>(out, b_out);
}